// round 12
// baseline (speedup 1.0000x reference)
#include <cuda_runtime.h>
#include <math.h>

// ============================================================================
// PlainFCOS post-process: top-1000 of sigmoid(cls_pred[80M]) + box gather.
//
// R11 changes vs R10 (65.6us; select 18.2us, dominated by the smem bitonic's
// 66 x 32KB shared-memory steps on a single SM):
//  - register-staged bitonic: warp w owns elements [64w,64w+64) as 2 regs per
//    lane. Steps j<=16 via 64-bit shfl_xor, j==32 in-thread, only j>=64 (15
//    of 66 steps) go through shared memory. Smem traffic ~3x lower; 51 steps
//    need no barriers at all.
//  - common path loads packed candidates straight into registers (no smem
//    staging round).
//  - collect (thr 4.15, 1184x256 unroll x8) unchanged: at its 77%-DRAM floor.
//  - rare paths (radix select for nn>2048, band re-scans for nn<1000) kept.
// Output layout: [bboxes 1000x4][scores 1000][labels 1000] as f32.
// ============================================================================

#define K_TOP      1000
#define CAND_CAP   (1u << 22)   // 4M entries (32 MB static)
#define SORT_CAP   2048
#define PRIMARY_THR  4.15f
#define BAND_LO      2.0f
#define SEL_THREADS  1024

__device__ unsigned int g_ncand;   // zero at load; k_select resets each call
__device__ unsigned long long g_pack[CAND_CAP];  // key<<32 | (0xFFFFFFFF - idx)

__device__ __forceinline__ unsigned int mono_key(float v) {
    unsigned int b = __float_as_uint(v);
    return b ^ ((b & 0x80000000u) ? 0xFFFFFFFFu : 0x80000000u);
}

__device__ __forceinline__ void emit(float v, unsigned idx, float lo, float hi) {
    if (v > lo && v <= hi) {
        unsigned p = atomicAdd(&g_ncand, 1u);
        if (p < CAND_CAP)
            g_pack[p] = ((unsigned long long)mono_key(v) << 32) |
                        (unsigned long long)(0xFFFFFFFFu - idx);
    }
}

__device__ __forceinline__ float max4(float4 a) {
    return fmaxf(fmaxf(a.x, a.y), fmaxf(a.z, a.w));
}

__device__ __forceinline__ void scan4(float4 a, unsigned base, float lo, float hi) {
    if (max4(a) > lo) {
        emit(a.x, base + 0u, lo, hi);
        emit(a.y, base + 1u, lo, hi);
        emit(a.z, base + 2u, lo, hi);
        emit(a.w, base + 3u, lo, hi);
    }
}

// Streaming collect: v > 4.15.  (R6-proven shape: 1184 x 256, unroll x8.)
__global__ void __launch_bounds__(256)
k_collect(const float* __restrict__ x, int n) {
    const float lo = PRIMARY_THR;
    const float hi = __int_as_float(0x7f800000);  // +inf

    const int n4 = n >> 2;
    const float4* __restrict__ x4 = reinterpret_cast<const float4*>(x);
    const int stride = gridDim.x * blockDim.x;
    int i = blockIdx.x * blockDim.x + threadIdx.x;

    for (; i + 7 * stride < n4; i += 8 * stride) {
        float4 v[8];
#pragma unroll
        for (int u = 0; u < 8; u++) v[u] = x4[i + u * stride];
        float m = max4(v[0]);
#pragma unroll
        for (int u = 1; u < 8; u++) m = fmaxf(m, max4(v[u]));
        if (m > lo) {
#pragma unroll
            for (int u = 0; u < 8; u++)
                scan4(v[u], 4u * (unsigned)(i + u * stride), lo, hi);
        }
    }
    for (; i < n4; i += stride)
        scan4(x4[i], 4u * (unsigned)i, lo, hi);
    {
        int tail = n & 3;
        int t = blockIdx.x * blockDim.x + threadIdx.x;
        if (t < tail) emit(x[(n4 << 2) + t], (unsigned)((n4 << 2) + t), lo, hi);
    }
}

// img_w / img_h may arrive as int32 or float32 scalars; disambiguate by range.
__device__ __forceinline__ float load_dim(const void* p) {
    int iv = *(const int*)p;
    if (iv > 0 && iv < (1 << 27)) return (float)iv;
    return *(const float*)p;
}

// One bitonic compare-exchange step on register pair (a,b) for lane-held
// elements at indices ia=64w+lane, ib=ia+32.  j <= 32 only.
__device__ __forceinline__ void reg_step(
    unsigned long long& a, unsigned long long& b,
    unsigned ia, unsigned ib, unsigned lane, unsigned sz, unsigned j) {
    if (j == 32u) {
        // in-thread pair; (ia & sz) == (ib & sz) since sz >= 64
        bool desc = ((ia & sz) == 0u);
        unsigned long long lo = (a < b) ? a : b;
        unsigned long long hi = (a < b) ? b : a;
        a = desc ? hi : lo;
        b = desc ? lo : hi;
    } else {
        unsigned long long pa = __shfl_xor_sync(0xFFFFFFFFu, a, j);
        unsigned long long pb = __shfl_xor_sync(0xFFFFFFFFu, b, j);
        bool lower = ((lane & j) == 0u);
        bool da = ((ia & sz) == 0u);
        bool db = ((ib & sz) == 0u);
        a = (lower == da) ? ((a > pa) ? a : pa) : ((a < pa) ? a : pa);
        b = (lower == db) ? ((b > pb) ? b : pb) : ((b < pb) ? b : pb);
    }
}

__global__ void __launch_bounds__(SEL_THREADS, 1)
k_select(const float* __restrict__ x, int n,
         const float* __restrict__ box,
         const void* __restrict__ pw, const void* __restrict__ ph,
         int nc, float* __restrict__ out) {
    __shared__ unsigned long long srt[SORT_CAP];   // 16KB sort buffer
    __shared__ unsigned int hist[256];
    __shared__ unsigned int sc[256];
    __shared__ unsigned int s_cnt, s_n;
    __shared__ unsigned int s_pref[2], s_rem[2];

    const int tid = threadIdx.x;
    const unsigned lane = (unsigned)tid & 31u;
    const int n4 = n >> 2;
    const float4* __restrict__ x4 = reinterpret_cast<const float4*>(x);

    // ---- rare fallback bands (never taken on bench input) ----
    {
        if (tid == 0) s_n = g_ncand;
        __syncthreads();
        if (s_n < (unsigned)K_TOP) {
            const float blo[2] = { BAND_LO, -__int_as_float(0x7f800000) };
            const float bhi[2] = { PRIMARY_THR, BAND_LO };
            for (int b = 0; b < 2; b++) {
                if (s_n >= (unsigned)K_TOP) break;
                for (unsigned i = tid; i < (unsigned)n4; i += SEL_THREADS)
                    scan4(x4[i], 4u * i, blo[b], bhi[b]);
                int tail = n & 3;
                if (tid < tail)
                    emit(x[(n4 << 2) + tid], (unsigned)((n4 << 2) + tid),
                         blo[b], bhi[b]);
                __syncthreads();
                if (tid == 0) s_n = g_ncand;
                __syncthreads();
            }
        }
    }

    const unsigned int nn = min(*(volatile unsigned int*)&g_ncand, CAND_CAP);
    const unsigned int k = min((unsigned)K_TOP, nn);

    // lane-held element indices: warp w owns [64w, 64w+64)
    const unsigned ia = (((unsigned)tid & ~31u) << 1) | lane;
    const unsigned ib = ia + 32u;
    unsigned long long a, b;

    if (nn <= (unsigned)SORT_CAP) {
        // ===== COMMON PATH: load packed candidates straight to registers =====
        a = (ia < nn) ? g_pack[ia] : 0ull;
        b = (ib < nn) ? g_pack[ib] : 0ull;
    } else {
        // ===== RARE PATH: MSD radix select + compact into smem, then load ====
        if (tid == 0) { s_pref[0] = 0u; s_rem[0] = k; s_cnt = 0u; }
        __syncthreads();
        int par = 0;
        for (int shift = 24; shift >= 0; shift -= 8, par ^= 1) {
            if (tid < 256) hist[tid] = 0u;
            __syncthreads();
            const unsigned prefix = s_pref[par];
            const unsigned mask_hi =
                (shift == 24) ? 0u : (0xFFFFFFFFu << (shift + 8));
            for (unsigned i = tid; i < nn; i += SEL_THREADS) {
                unsigned key = (unsigned)(g_pack[i] >> 32);
                if ((key & mask_hi) == prefix)
                    atomicAdd(&hist[(key >> shift) & 255u], 1u);
            }
            __syncthreads();
            if (tid < 32) {
                unsigned bb[8], ss[8];
#pragma unroll
                for (int j = 0; j < 8; j++) bb[j] = hist[tid * 8 + j];
                ss[7] = bb[7];
#pragma unroll
                for (int j = 6; j >= 0; j--) ss[j] = ss[j + 1] + bb[j];
                unsigned total = ss[0];
                unsigned incl = total;
#pragma unroll
                for (int off = 1; off < 32; off <<= 1) {
                    unsigned v = __shfl_down_sync(0xFFFFFFFFu, incl, off);
                    if (tid + off < 32) incl += v;
                }
                unsigned above_lane = incl - total;
#pragma unroll
                for (int j = 0; j < 8; j++) sc[tid * 8 + j] = ss[j] + above_lane;
            }
            __syncthreads();
            if (tid < 256) {
                unsigned rem = s_rem[par];
                unsigned here = sc[tid];
                unsigned above = (tid == 255) ? 0u : sc[tid + 1];
                if (here >= rem && above < rem) {
                    s_rem[par ^ 1]  = rem - above;
                    s_pref[par ^ 1] = prefix | ((unsigned)tid << shift);
                }
            }
            __syncthreads();
        }
        const unsigned int Kstar = s_pref[0];
        for (unsigned i = tid; i < nn; i += SEL_THREADS) {
            unsigned long long v = g_pack[i];
            if ((unsigned)(v >> 32) >= Kstar) {
                unsigned p = atomicAdd(&s_cnt, 1u);
                if (p < SORT_CAP) srt[p] = v;
            }
        }
        __syncthreads();
        const unsigned mm = min(s_cnt, (unsigned)SORT_CAP);
        for (unsigned i = tid; i < (unsigned)SORT_CAP; i += SEL_THREADS)
            if (i >= mm) srt[i] = 0ull;
        __syncthreads();
        a = srt[ia];
        b = srt[ib];
    }

    // ---- register phases: sz = 2..64 (all steps warp-internal) ----
#pragma unroll
    for (unsigned sz = 2; sz <= 64; sz <<= 1)
        for (unsigned j = sz >> 1; j > 0; j >>= 1)
            reg_step(a, b, ia, ib, lane, sz, j);

    // ---- mixed phases: sz = 128..2048 ----
    for (unsigned sz = 128; sz <= (unsigned)SORT_CAP; sz <<= 1) {
        srt[ia] = a;
        srt[ib] = b;
        __syncthreads();
        for (unsigned j = sz >> 1; j >= 64; j >>= 1) {
            unsigned t = (unsigned)tid;
            unsigned i = ((t & ~(j - 1u)) << 1) | (t & (j - 1u));
            unsigned ixj = i | j;
            unsigned long long va = srt[i], vb = srt[ixj];
            bool desc = ((i & sz) == 0u);
            if (desc ? (va < vb) : (va > vb)) { srt[i] = vb; srt[ixj] = va; }
            __syncthreads();
        }
        a = srt[ia];
        b = srt[ib];
#pragma unroll
        for (unsigned j = 32; j > 0; j >>= 1)
            reg_step(a, b, ia, ib, lane, sz, j);
    }
    srt[ia] = a;
    srt[ib] = b;
    __syncthreads();

    // ---- decode winners, gather + normalize boxes, write outputs ----
    const float fw = load_dim(pw);
    const float fh = load_dim(ph);
    const unsigned int valid = k;
    const float4* __restrict__ box4 = reinterpret_cast<const float4*>(box);

    for (unsigned i = tid; i < (unsigned)K_TOP; i += SEL_THREADS) {
        float b0 = 0.f, b1 = 0.f, b2 = 0.f, b3 = 0.f, scv = 0.f, lab = 0.f;
        if (i < valid) {
            unsigned long long e = srt[i];
            unsigned key = (unsigned)(e >> 32);
            unsigned idx = 0xFFFFFFFFu - (unsigned)(e & 0xFFFFFFFFull);
            unsigned bits = (key & 0x80000000u) ? (key ^ 0x80000000u) : ~key;
            float v = __uint_as_float(bits);
            scv = 1.0f / (1.0f + __expf(-v));
            unsigned bi = idx / (unsigned)nc;
            lab = (float)(idx - bi * (unsigned)nc);
            float4 bb = box4[bi];
            b0 = fminf(fmaxf(bb.x / fw, 0.f), 1.f);
            b1 = fminf(fmaxf(bb.y / fh, 0.f), 1.f);
            b2 = fminf(fmaxf(bb.z / fw, 0.f), 1.f);
            b3 = fminf(fmaxf(bb.w / fh, 0.f), 1.f);
        }
        out[i * 4 + 0] = b0;
        out[i * 4 + 1] = b1;
        out[i * 4 + 2] = b2;
        out[i * 4 + 3] = b3;
        out[4 * K_TOP + i] = scv;
        out[5 * K_TOP + i] = lab;
    }

    // reset global state for the next graph replay
    __syncthreads();
    if (tid == 0) g_ncand = 0u;
}

extern "C" void kernel_launch(void* const* d_in, const int* in_sizes, int n_in,
                              void* d_out, int out_size) {
    const float* cls = (const float*)d_in[0];
    const float* box = (const float*)d_in[1];
    const void* pw = (n_in > 3) ? d_in[3] : nullptr;
    const void* ph = (n_in > 4) ? d_in[4] : nullptr;

    int n = in_sizes[0];                       // Nq * Nc
    int nbox = (n_in > 1) ? in_sizes[1] : 4;   // Nq * 4
    int nq = nbox / 4;
    int nc = (nq > 0) ? (n / nq) : 80;

    k_collect<<<1184, 256>>>(cls, n);
    k_select<<<1, SEL_THREADS>>>(cls, n, box, pw, ph, nc, (float*)d_out);
}

// round 14
// speedup vs baseline: 1.0250x; 1.0250x over previous
#include <cuda_runtime.h>
#include <math.h>

// ============================================================================
// PlainFCOS post-process: top-1000 of sigmoid(cls_pred[80M]) + box gather.
//
// R13 changes vs R12 (65.6us): select's ~11us real cost is mostly fixed
// serial overhead (launch gap, cold I$/L1 on a grid=1 kernel, dependent L2
// rounds), not its loops (3 neutral loop-optimizations prove it). So:
//  - k_select is launched with PROGRAMMATIC DEPENDENT LAUNCH (PSS attribute);
//    its collect-independent prologue (img_w/img_h loads, index setup, I$
//    warmup) overlaps collect's tail; cudaGridDependencySynchronize() gates
//    the first read of g_ncand/g_pack (PDL guarantees visibility).
//  - band-check reads g_ncand via per-thread __ldcg broadcast (-2 barriers).
//  - collect (thr 4.15, 1184x256, unroll x8) byte-identical: at 77.9% DRAM.
//  - register-staged bitonic, rare radix path, fallback bands unchanged.
// Output layout: [bboxes 1000x4][scores 1000][labels 1000] as f32.
// ============================================================================

#define K_TOP      1000
#define CAND_CAP   (1u << 22)   // 4M entries (32 MB static)
#define SORT_CAP   2048
#define PRIMARY_THR  4.15f
#define BAND_LO      2.0f
#define SEL_THREADS  1024

__device__ unsigned int g_ncand;   // zero at load; k_select resets each call
__device__ unsigned long long g_pack[CAND_CAP];  // key<<32 | (0xFFFFFFFF - idx)

__device__ __forceinline__ unsigned int mono_key(float v) {
    unsigned int b = __float_as_uint(v);
    return b ^ ((b & 0x80000000u) ? 0xFFFFFFFFu : 0x80000000u);
}

__device__ __forceinline__ void emit(float v, unsigned idx, float lo, float hi) {
    if (v > lo && v <= hi) {
        unsigned p = atomicAdd(&g_ncand, 1u);
        if (p < CAND_CAP)
            g_pack[p] = ((unsigned long long)mono_key(v) << 32) |
                        (unsigned long long)(0xFFFFFFFFu - idx);
    }
}

__device__ __forceinline__ float max4(float4 a) {
    return fmaxf(fmaxf(a.x, a.y), fmaxf(a.z, a.w));
}

__device__ __forceinline__ void scan4(float4 a, unsigned base, float lo, float hi) {
    if (max4(a) > lo) {
        emit(a.x, base + 0u, lo, hi);
        emit(a.y, base + 1u, lo, hi);
        emit(a.z, base + 2u, lo, hi);
        emit(a.w, base + 3u, lo, hi);
    }
}

// Streaming collect: v > 4.15.  (R6-proven shape: 1184 x 256, unroll x8.)
__global__ void __launch_bounds__(256)
k_collect(const float* __restrict__ x, int n) {
    const float lo = PRIMARY_THR;
    const float hi = __int_as_float(0x7f800000);  // +inf

    const int n4 = n >> 2;
    const float4* __restrict__ x4 = reinterpret_cast<const float4*>(x);
    const int stride = gridDim.x * blockDim.x;
    int i = blockIdx.x * blockDim.x + threadIdx.x;

    for (; i + 7 * stride < n4; i += 8 * stride) {
        float4 v[8];
#pragma unroll
        for (int u = 0; u < 8; u++) v[u] = x4[i + u * stride];
        float m = max4(v[0]);
#pragma unroll
        for (int u = 1; u < 8; u++) m = fmaxf(m, max4(v[u]));
        if (m > lo) {
#pragma unroll
            for (int u = 0; u < 8; u++)
                scan4(v[u], 4u * (unsigned)(i + u * stride), lo, hi);
        }
    }
    for (; i < n4; i += stride)
        scan4(x4[i], 4u * (unsigned)i, lo, hi);
    {
        int tail = n & 3;
        int t = blockIdx.x * blockDim.x + threadIdx.x;
        if (t < tail) emit(x[(n4 << 2) + t], (unsigned)((n4 << 2) + t), lo, hi);
    }
}

// img_w / img_h may arrive as int32 or float32 scalars; disambiguate by range.
__device__ __forceinline__ float load_dim(const void* p) {
    int iv = *(const int*)p;
    if (iv > 0 && iv < (1 << 27)) return (float)iv;
    return *(const float*)p;
}

// One bitonic compare-exchange step on register pair (a,b) for lane-held
// elements at indices ia=64w+lane, ib=ia+32.  j <= 32 only.
__device__ __forceinline__ void reg_step(
    unsigned long long& a, unsigned long long& b,
    unsigned ia, unsigned ib, unsigned lane, unsigned sz, unsigned j) {
    if (j == 32u) {
        bool desc = ((ia & sz) == 0u);
        unsigned long long lo = (a < b) ? a : b;
        unsigned long long hi = (a < b) ? b : a;
        a = desc ? hi : lo;
        b = desc ? lo : hi;
    } else {
        unsigned long long pa = __shfl_xor_sync(0xFFFFFFFFu, a, j);
        unsigned long long pb = __shfl_xor_sync(0xFFFFFFFFu, b, j);
        bool lower = ((lane & j) == 0u);
        bool da = ((ia & sz) == 0u);
        bool db = ((ib & sz) == 0u);
        a = (lower == da) ? ((a > pa) ? a : pa) : ((a < pa) ? a : pa);
        b = (lower == db) ? ((b > pb) ? b : pb) : ((b < pb) ? b : pb);
    }
}

__global__ void __launch_bounds__(SEL_THREADS, 1)
k_select(const float* __restrict__ x, int n,
         const float* __restrict__ box,
         const void* __restrict__ pw, const void* __restrict__ ph,
         int nc, float* __restrict__ out) {
    __shared__ unsigned long long srt[SORT_CAP];   // 16KB sort buffer
    __shared__ unsigned int hist[256];
    __shared__ unsigned int sc[256];
    __shared__ unsigned int s_cnt;
    __shared__ unsigned int s_pref[2], s_rem[2];

    const int tid = threadIdx.x;
    const unsigned lane = (unsigned)tid & 31u;
    const int n4 = n >> 2;
    const float4* __restrict__ x4 = reinterpret_cast<const float4*>(x);

    // ---- PDL prologue: everything that does NOT depend on collect ----
    const float fw = load_dim(pw);
    const float fh = load_dim(ph);
    const unsigned ia = (((unsigned)tid & ~31u) << 1) | lane;  // warp w owns [64w,64w+64)
    const unsigned ib = ia + 32u;
    if (tid == 0) s_cnt = 0u;

    // gate: all of collect's g_pack/g_ncand writes become visible after this
    cudaGridDependencySynchronize();

    // ---- rare fallback bands (never taken on bench input) ----
    {
        unsigned cur = __ldcg(&g_ncand);   // broadcast load, no barrier needed
        if (cur < (unsigned)K_TOP) {
            const float blo[2] = { BAND_LO, -__int_as_float(0x7f800000) };
            const float bhi[2] = { PRIMARY_THR, BAND_LO };
            for (int b = 0; b < 2; b++) {
                if (cur >= (unsigned)K_TOP) break;
                for (unsigned i = tid; i < (unsigned)n4; i += SEL_THREADS)
                    scan4(x4[i], 4u * i, blo[b], bhi[b]);
                int tail = n & 3;
                if (tid < tail)
                    emit(x[(n4 << 2) + tid], (unsigned)((n4 << 2) + tid),
                         blo[b], bhi[b]);
                __syncthreads();
                cur = __ldcg(&g_ncand);
                __syncthreads();
            }
        }
    }

    const unsigned int nn = min(__ldcg(&g_ncand), CAND_CAP);
    const unsigned int k = min((unsigned)K_TOP, nn);
    unsigned long long a, b;

    if (nn <= (unsigned)SORT_CAP) {
        // ===== COMMON PATH: load packed candidates straight to registers =====
        a = (ia < nn) ? g_pack[ia] : 0ull;
        b = (ib < nn) ? g_pack[ib] : 0ull;
    } else {
        // ===== RARE PATH: MSD radix select + compact into smem, then load ====
        if (tid == 0) { s_pref[0] = 0u; s_rem[0] = k; }
        __syncthreads();
        int par = 0;
        for (int shift = 24; shift >= 0; shift -= 8, par ^= 1) {
            if (tid < 256) hist[tid] = 0u;
            __syncthreads();
            const unsigned prefix = s_pref[par];
            const unsigned mask_hi =
                (shift == 24) ? 0u : (0xFFFFFFFFu << (shift + 8));
            for (unsigned i = tid; i < nn; i += SEL_THREADS) {
                unsigned key = (unsigned)(g_pack[i] >> 32);
                if ((key & mask_hi) == prefix)
                    atomicAdd(&hist[(key >> shift) & 255u], 1u);
            }
            __syncthreads();
            if (tid < 32) {
                unsigned bb[8], ss[8];
#pragma unroll
                for (int j = 0; j < 8; j++) bb[j] = hist[tid * 8 + j];
                ss[7] = bb[7];
#pragma unroll
                for (int j = 6; j >= 0; j--) ss[j] = ss[j + 1] + bb[j];
                unsigned total = ss[0];
                unsigned incl = total;
#pragma unroll
                for (int off = 1; off < 32; off <<= 1) {
                    unsigned v = __shfl_down_sync(0xFFFFFFFFu, incl, off);
                    if (tid + off < 32) incl += v;
                }
                unsigned above_lane = incl - total;
#pragma unroll
                for (int j = 0; j < 8; j++) sc[tid * 8 + j] = ss[j] + above_lane;
            }
            __syncthreads();
            if (tid < 256) {
                unsigned rem = s_rem[par];
                unsigned here = sc[tid];
                unsigned above = (tid == 255) ? 0u : sc[tid + 1];
                if (here >= rem && above < rem) {
                    s_rem[par ^ 1]  = rem - above;
                    s_pref[par ^ 1] = prefix | ((unsigned)tid << shift);
                }
            }
            __syncthreads();
        }
        const unsigned int Kstar = s_pref[0];
        for (unsigned i = tid; i < nn; i += SEL_THREADS) {
            unsigned long long v = g_pack[i];
            if ((unsigned)(v >> 32) >= Kstar) {
                unsigned p = atomicAdd(&s_cnt, 1u);
                if (p < SORT_CAP) srt[p] = v;
            }
        }
        __syncthreads();
        const unsigned mm = min(s_cnt, (unsigned)SORT_CAP);
        for (unsigned i = tid; i < (unsigned)SORT_CAP; i += SEL_THREADS)
            if (i >= mm) srt[i] = 0ull;
        __syncthreads();
        a = srt[ia];
        b = srt[ib];
    }

    // ---- register phases: sz = 2..64 (all steps warp-internal) ----
#pragma unroll
    for (unsigned sz = 2; sz <= 64; sz <<= 1)
        for (unsigned j = sz >> 1; j > 0; j >>= 1)
            reg_step(a, b, ia, ib, lane, sz, j);

    // ---- mixed phases: sz = 128..2048 ----
    for (unsigned sz = 128; sz <= (unsigned)SORT_CAP; sz <<= 1) {
        srt[ia] = a;
        srt[ib] = b;
        __syncthreads();
        for (unsigned j = sz >> 1; j >= 64; j >>= 1) {
            unsigned t = (unsigned)tid;
            unsigned i = ((t & ~(j - 1u)) << 1) | (t & (j - 1u));
            unsigned ixj = i | j;
            unsigned long long va = srt[i], vb = srt[ixj];
            bool desc = ((i & sz) == 0u);
            if (desc ? (va < vb) : (va > vb)) { srt[i] = vb; srt[ixj] = va; }
            __syncthreads();
        }
        a = srt[ia];
        b = srt[ib];
#pragma unroll
        for (unsigned j = 32; j > 0; j >>= 1)
            reg_step(a, b, ia, ib, lane, sz, j);
    }
    srt[ia] = a;
    srt[ib] = b;
    __syncthreads();

    // ---- decode winners, gather + normalize boxes, write outputs ----
    const unsigned int valid = k;
    const float4* __restrict__ box4 = reinterpret_cast<const float4*>(box);

    for (unsigned i = tid; i < (unsigned)K_TOP; i += SEL_THREADS) {
        float b0 = 0.f, b1 = 0.f, b2 = 0.f, b3 = 0.f, scv = 0.f, lab = 0.f;
        if (i < valid) {
            unsigned long long e = srt[i];
            unsigned key = (unsigned)(e >> 32);
            unsigned idx = 0xFFFFFFFFu - (unsigned)(e & 0xFFFFFFFFull);
            unsigned bits = (key & 0x80000000u) ? (key ^ 0x80000000u) : ~key;
            float v = __uint_as_float(bits);
            scv = 1.0f / (1.0f + __expf(-v));
            unsigned bi = idx / (unsigned)nc;
            lab = (float)(idx - bi * (unsigned)nc);
            float4 bb = box4[bi];
            b0 = fminf(fmaxf(bb.x / fw, 0.f), 1.f);
            b1 = fminf(fmaxf(bb.y / fh, 0.f), 1.f);
            b2 = fminf(fmaxf(bb.z / fw, 0.f), 1.f);
            b3 = fminf(fmaxf(bb.w / fh, 0.f), 1.f);
        }
        out[i * 4 + 0] = b0;
        out[i * 4 + 1] = b1;
        out[i * 4 + 2] = b2;
        out[i * 4 + 3] = b3;
        out[4 * K_TOP + i] = scv;
        out[5 * K_TOP + i] = lab;
    }

    // reset global state for the next graph replay
    __syncthreads();
    if (tid == 0) g_ncand = 0u;
}

extern "C" void kernel_launch(void* const* d_in, const int* in_sizes, int n_in,
                              void* d_out, int out_size) {
    const float* cls = (const float*)d_in[0];
    const float* box = (const float*)d_in[1];
    const void* pw = (n_in > 3) ? d_in[3] : nullptr;
    const void* ph = (n_in > 4) ? d_in[4] : nullptr;

    int n = in_sizes[0];                       // Nq * Nc
    int nbox = (n_in > 1) ? in_sizes[1] : 4;   // Nq * 4
    int nq = nbox / 4;
    int nc = (nq > 0) ? (n / nq) : 80;

    k_collect<<<1184, 256>>>(cls, n);

    // Programmatic dependent launch: select's prologue overlaps collect's
    // tail; cudaGridDependencySynchronize() inside gates data consumption.
    cudaLaunchAttribute attrs[1];
    attrs[0].id = cudaLaunchAttributeProgrammaticStreamSerialization;
    attrs[0].val.programmaticStreamSerializationAllowed = 1;
    cudaLaunchConfig_t cfg = {};
    cfg.gridDim = dim3(1, 1, 1);
    cfg.blockDim = dim3(SEL_THREADS, 1, 1);
    cfg.dynamicSmemBytes = 0;
    cfg.stream = 0;
    cfg.attrs = attrs;
    cfg.numAttrs = 1;
    cudaLaunchKernelEx(&cfg, k_select, cls, n, box, pw, ph, nc, (float*)d_out);
}